// round 8
// baseline (speedup 1.0000x reference)
#include <cuda_runtime.h>

#define BLK 256
#define NCHUNK 24

// SMEM layout (floats):
//  x2s   : [24][11][16]      @ 0     (4224)
//  cgs   : [11][11][11]      @ 4224  (1332, padded)
//  Ws    : [24 k][36 h-pad]  @ 5556  (864)
//  x1col : [2][11][16]       @ 6420  (352)   double-buffered x1 column
//  us    : ull[121][8]       @ 6772  (1936)  u = cg * x1, shared across d
//  cats  : ull[24][N][8]     @ 8708  (4224 max @ N=11)
#define SMEM_FLOATS 12932
#define SMEM_BYTES (SMEM_FLOATS * 4)

typedef unsigned long long ull;

__device__ __forceinline__ ull pack2(float v) {
    ull r; asm("mov.b64 %0, {%1, %1};" : "=l"(r) : "f"(v)); return r;
}
__device__ __forceinline__ ull mul2(ull a, ull b) {
    ull r; asm("mul.rn.f32x2 %0, %1, %2;" : "=l"(r) : "l"(a), "l"(b)); return r;
}
__device__ __forceinline__ ull fma2(ull a, ull b, ull c) {
    ull r; asm("fma.rn.f32x2 %0, %1, %2, %3;" : "=l"(r) : "l"(a), "l"(b), "l"(c)); return r;
}
__device__ __forceinline__ void unpack2(ull v, float& lo, float& hi) {
    asm("mov.b64 {%0, %1}, %2;" : "=f"(lo), "=f"(hi) : "l"(v));
}

__device__ __forceinline__ const float* pick6(
    const float* a0, const float* a1, const float* a2,
    const float* a3, const float* a4, const float* a5, int l) {
    switch (l) {
        case 0: return a0; case 1: return a1; case 2: return a2;
        case 3: return a3; case 4: return a4; default: return a5;
    }
}

template <int N>
__device__ __forceinline__ void run_pair(
    const float* __restrict__ Xa,        // global x_{l1} (for column staging)
    const float* __restrict__ x2s,
    const float* __restrict__ cgs,
    float* __restrict__ Ws,
    float* __restrict__ x1col,
    ull* __restrict__ us,
    ull* __restrict__ cats64,
    const float* __restrict__ Wl, int KIN, int koff,
    int n1, int n2, int cbase,
    float* __restrict__ out, int b0, int moff)
{
    const int tid = threadIdx.x;
    const int bp = tid & 7;          // batch pair 0..7 (f32x2)
    const int hg = (tid >> 3) & 7;   // h quad: h = hg*4 + j
    const int ms = tid >> 6;         // m slice 0..3: mi = ms + 4*mj
    const int rr = tid >> 3;         // 0..31: row cursor

    constexpr int MS = (N + 3) / 4;
    ull acc[4][MS];
#pragma unroll
    for (int j = 0; j < 4; ++j)
#pragma unroll
        for (int mj = 0; mj < MS; ++mj) acc[j][mj] = 0ull;

    const ull* __restrict__ x2s64 = (const ull*)x2s;
    const ull* __restrict__ x1c64 = (const ull*)x1col;
    const unsigned n2u = (unsigned)n2;
    const int x1stride = 24 * n1;

#pragma unroll 1
    for (int cc = 0; cc < NCHUNK; ++cc) {
        const int par = cc & 1;
        // --- A: W chunk load, [32 h][24 d] global-coalesced -> Ws[d*36+h] ---
#pragma unroll
        for (int i = tid; i < 768; i += BLK) {
            const int h = i / 24;
            const int d = i - h * 24;
            Ws[d * 36 + h] = Wl[h * KIN + koff + cc * 24 + d];
        }
        // --- A: u build: u[mi][m1i][bp] = cg[mi,m1i,m2i] * x1[cc][m1i][bp] ---
#pragma unroll
        for (int t = 0; t < 4; ++t) {
            const int s = rr + 32 * t;
            if (s < 121) {
                const int mi  = s / 11;
                const int m1i = s - mi * 11;
                const int m2i = mi + cbase - m1i;
                const bool valid = (mi < N) & (m1i < n1) & ((unsigned)m2i < n2u);
                float cgv = 0.f;
                if (valid) cgv = cgs[mi * 121 + m1i * 11 + m2i];
                const ull xv = x1c64[par * 88 + m1i * 8 + bp];
                us[s * 8 + bp] = valid ? mul2(pack2(cgv), xv) : 0ull;
            }
        }
        __syncthreads();
        // --- B: cat rows: cat[d][mi][bp] = sum_m1 u[mi][m1] * x2[d][m2] ---
#pragma unroll 1
        for (int row = rr; row < 24 * N; row += 32) {
            const int d  = row / N;               // compile-time divisor
            const int mi = row - d * N;
            const int base = mi + cbase;          // m2i = base - m1i
            const ull* __restrict__ up  = us + mi * 88 + bp;              // +m1i*8
            const ull* __restrict__ x2q = x2s64 + d * 88 + bp + base * 8; // -m1i*8
            ull v = 0ull;
#pragma unroll
            for (int m1i = 0; m1i < 11; ++m1i) {
                if (m1i >= n1) break;             // uniform across CTA
                if ((unsigned)(base - m1i) < n2u)
                    v = fma2(up[m1i * 8], x2q[-(m1i * 8)], v);
            }
            cats64[row * 8 + bp] = v;
        }
        __syncthreads();
        // --- C: stage next x1 column (hidden under GEMM) ---
        if (cc + 1 < NCHUNK && tid < 16 * n1) {
            const int m1i = tid >> 4;
            const int b   = tid & 15;
            x1col[(par ^ 1) * 176 + m1i * 16 + b] =
                Xa[(b0 + b) * x1stride + (cc + 1) * n1 + m1i];
        }
        // --- C: GEMM (R6 exact body, k<24): acc += W[h,k]*cat[k,mi,bp] ---
#pragma unroll 4
        for (int k = 0; k < 24; ++k) {
            const float4 w = *reinterpret_cast<const float4*>(&Ws[k * 36 + hg * 4]);
            const ull w2[4] = { pack2(w.x), pack2(w.y), pack2(w.z), pack2(w.w) };
            const ull* __restrict__ cp = cats64 + k * (8 * N) + bp;
#pragma unroll
            for (int mj = 0; mj < MS; ++mj) {
                const int mi = ms + 4 * mj;
                if (mi < N) {                      // warp-uniform
                    const ull cv = cp[mi * 8];
                    acc[0][mj] = fma2(w2[0], cv, acc[0][mj]);
                    acc[1][mj] = fma2(w2[1], cv, acc[1][mj]);
                    acc[2][mj] = fma2(w2[2], cv, acc[2][mj]);
                    acc[3][mj] = fma2(w2[3], cv, acc[3][mj]);
                }
            }
        }
        __syncthreads();
    }

    // --- writeback: batches b0+2bp, b0+2bp+1 ---
    float* op = out + ((b0 + bp * 2) * 32 + hg * 4) * 36 + moff;
#pragma unroll
    for (int j = 0; j < 4; ++j) {
#pragma unroll
        for (int mj = 0; mj < MS; ++mj) {
            const int mi = ms + 4 * mj;
            if (mi < N) {
                float lo, hi;
                unpack2(acc[j][mj], lo, hi);
                atomicAdd(op + j * 36 + mi, lo);
                atomicAdd(op + 32 * 36 + j * 36 + mi, hi);
            }
        }
    }
}

__global__ void __launch_bounds__(BLK, 4) cg_main(
    const float* __restrict__ X0, const float* __restrict__ X1, const float* __restrict__ X2,
    const float* __restrict__ X3, const float* __restrict__ X4, const float* __restrict__ X5,
    const float* __restrict__ W0, const float* __restrict__ W1, const float* __restrict__ W2,
    const float* __restrict__ W3, const float* __restrict__ W4, const float* __restrict__ W5,
    const float* __restrict__ cg, float* __restrict__ out)
{
    extern __shared__ float sm[];
    float* x2s   = sm;
    float* cgs   = sm + 4224;
    float* Ws    = sm + 5556;
    float* x1col = sm + 6420;
    ull*   us    = (ull*)(sm + 6772);
    ull*   cats  = (ull*)(sm + 8708);

    const int item = blockIdx.x >> 4;          // 0..110 (l, pair)
    const int b0   = (blockIdx.x & 15) << 4;   // batch tile start

    // decode work item: l ordered 5,4,3,2,1,0 (big work first)
    int l = 0, l1 = 0, l2 = 0, pidx = 0;
    {
        int cur = 0;
        bool done = false;
        for (int oi = 0; oi < 6 && !done; ++oi) {
            int L = 5 - oi;
            int pi = 0;
            for (int a = 0; a <= 5 && !done; ++a) {
                for (int b2 = 0; b2 <= 5; ++b2) {
                    int dd = a - b2; if (dd < 0) dd = -dd;
                    if (dd <= L && L <= a + b2) {
                        if (cur == item) { l = L; l1 = a; l2 = b2; pidx = pi; done = true; break; }
                        ++cur; ++pi;
                    }
                }
            }
        }
    }

    const int n1 = 2 * l1 + 1, n2 = 2 * l2 + 1, n = 2 * l + 1;
    int KIN, moff;
    switch (l) {
        case 0: KIN = 3456;  moff = 0;  break;
        case 1: KIN = 8640;  moff = 1;  break;
        case 2: KIN = 12096; moff = 4;  break;
        case 3: KIN = 13824; moff = 9;  break;
        case 4: KIN = 13824; moff = 16; break;
        default: KIN = 12096; moff = 25; break;
    }
    const float* Xa = pick6(X0, X1, X2, X3, X4, X5, l1);
    const float* Xb = pick6(X0, X1, X2, X3, X4, X5, l2);
    const float* Wl = pick6(W0, W1, W2, W3, W4, W5, l);
    const int koff = pidx * 576;
    const int tid = threadIdx.x;

    // load x2 tile: global (b,d,m2) -> smem [d][m2][b16]
    for (int i = tid; i < 16 * 24 * n2; i += BLK) {
        int b = i / (24 * n2);
        int r = i - b * 24 * n2;
        int d = r / n2;
        int m2 = r - d * n2;
        x2s[(d * 11 + m2) * 16 + b] = Xb[(b0 + b) * 24 * n2 + r];
    }
    // cg slab for (l1,l2,l): contiguous n*121 floats
    const float* cgp = cg + ((l1 * 6 + l2) * 6 + l) * 1331;
    for (int i = tid; i < n * 121; i += BLK) cgs[i] = cgp[i];
    // stage x1 column for cc=0 into buffer 0
    if (tid < 16 * n1) {
        const int m1i = tid >> 4;
        const int b   = tid & 15;
        x1col[m1i * 16 + b] = Xa[(b0 + b) * (24 * n1) + m1i];
    }
    __syncthreads();

    const int cbase = l1 + l2 - l;
    switch (l) {
        case 0: run_pair<1>(Xa, x2s, cgs, Ws, x1col, us, cats, Wl, KIN, koff, n1, n2, cbase, out, b0, moff); break;
        case 1: run_pair<3>(Xa, x2s, cgs, Ws, x1col, us, cats, Wl, KIN, koff, n1, n2, cbase, out, b0, moff); break;
        case 2: run_pair<5>(Xa, x2s, cgs, Ws, x1col, us, cats, Wl, KIN, koff, n1, n2, cbase, out, b0, moff); break;
        case 3: run_pair<7>(Xa, x2s, cgs, Ws, x1col, us, cats, Wl, KIN, koff, n1, n2, cbase, out, b0, moff); break;
        case 4: run_pair<9>(Xa, x2s, cgs, Ws, x1col, us, cats, Wl, KIN, koff, n1, n2, cbase, out, b0, moff); break;
        default: run_pair<11>(Xa, x2s, cgs, Ws, x1col, us, cats, Wl, KIN, koff, n1, n2, cbase, out, b0, moff); break;
    }
}

__global__ void zero_out_kernel(float* __restrict__ o, int nTot) {
    int i = blockIdx.x * 256 + threadIdx.x;
    if (i < nTot) o[i] = 0.f;
}

extern "C" void kernel_launch(void* const* d_in, const int* in_sizes, int n_in,
                              void* d_out, int out_size)
{
    const float* X[6];
    const float* W[6];
    for (int i = 0; i < 6; ++i) X[i] = (const float*)d_in[i];
    for (int i = 0; i < 6; ++i) W[i] = (const float*)d_in[6 + i];
    const float* cg = (const float*)d_in[12];
    float* out = (float*)d_out;

    const int nTot = 256 * 32 * 36;  // 294912
    zero_out_kernel<<<(nTot + 255) / 256, 256>>>(out, nTot);

    cudaFuncSetAttribute(cg_main, cudaFuncAttributeMaxDynamicSharedMemorySize, SMEM_BYTES);
    cg_main<<<111 * 16, BLK, SMEM_BYTES>>>(
        X[0], X[1], X[2], X[3], X[4], X[5],
        W[0], W[1], W[2], W[3], W[4], W[5],
        cg, out);
}

// round 9
// speedup vs baseline: 1.0603x; 1.0603x over previous
#include <cuda_runtime.h>

#define BLK 256
#define NCHUNK 24

// SMEM layout (floats):
//  x2s   : [24][11][16]      @ 0     (4224)  zero-init
//  cgs   : [11][11][11]      @ 4224  (1332, padded)
//  Ws    : [24 d][36 h-pad]  @ 5556  (864)
//  x1col : [2][11][16]       @ 6420  (352)   double-buffered, zero-init
//  As    : ull[121][8]       @ 6772  (1936)  A[mi][m2] = cg*x1
//  cats  : ull[24][N][8]     @ 8708  (4224 max @ N=11)
#define SMEM_FLOATS 12932
#define SMEM_BYTES (SMEM_FLOATS * 4)

typedef unsigned long long ull;

__device__ __forceinline__ ull pack2(float v) {
    ull r; asm("mov.b64 %0, {%1, %1};" : "=l"(r) : "f"(v)); return r;
}
__device__ __forceinline__ ull mul2(ull a, ull b) {
    ull r; asm("mul.rn.f32x2 %0, %1, %2;" : "=l"(r) : "l"(a), "l"(b)); return r;
}
__device__ __forceinline__ ull fma2(ull a, ull b, ull c) {
    ull r; asm("fma.rn.f32x2 %0, %1, %2, %3;" : "=l"(r) : "l"(a), "l"(b), "l"(c)); return r;
}
__device__ __forceinline__ void unpack2(ull v, float& lo, float& hi) {
    asm("mov.b64 {%0, %1}, %2;" : "=f"(lo), "=f"(hi) : "l"(v));
}

__device__ __forceinline__ const float* pick6(
    const float* a0, const float* a1, const float* a2,
    const float* a3, const float* a4, const float* a5, int l) {
    switch (l) {
        case 0: return a0; case 1: return a1; case 2: return a2;
        case 3: return a3; case 4: return a4; default: return a5;
    }
}

template <int N>
__device__ __forceinline__ void run_pair(
    const float* __restrict__ Xa,        // global x_{l1} (column staging)
    const float* __restrict__ x2s,
    const float* __restrict__ cgs,
    float* __restrict__ Ws,
    float* __restrict__ x1col,
    ull* __restrict__ As,
    ull* __restrict__ cats64,
    const float* __restrict__ Wl, int KIN, int koff,
    int n1, int cbase,
    float* __restrict__ out, int b0, int moff)
{
    const int tid = threadIdx.x;
    const int bp = tid & 7;          // batch pair 0..7 (f32x2)
    const int hg = (tid >> 3) & 7;   // h quad: h = hg*4 + j
    const int ms = tid >> 6;         // m slice 0..3 (GEMM): mi = ms + 4*mj
    const int rr = tid >> 3;         // 0..31 cursor
    const int dg  = rr >> 2;         // 0..7: d group (3 d each) for build-GEMM
    const int ms2 = rr & 3;          // 0..3: mi slice for build-GEMM

    constexpr int MS = (N + 3) / 4;
    ull acc[4][MS];
#pragma unroll
    for (int j = 0; j < 4; ++j)
#pragma unroll
        for (int mj = 0; mj < MS; ++mj) acc[j][mj] = 0ull;

    const ull* __restrict__ x2s64 = (const ull*)x2s;
    const ull* __restrict__ x1c64 = (const ull*)x1col;
    const unsigned n1u = (unsigned)n1;
    const int x1stride = 24 * n1;

#pragma unroll 1
    for (int cc = 0; cc < NCHUNK; ++cc) {
        const int par = cc & 1;
        // ---- phase 1: W chunk load + A build ----
#pragma unroll
        for (int i = tid; i < 768; i += BLK) {
            const int h = i / 24;
            const int d = i - h * 24;
            Ws[d * 36 + h] = Wl[h * KIN + koff + cc * 24 + d];
        }
        // A[mi][m2][bp] = cg[mi, m1=mi+cb-m2, m2] * x1[cc][m1][bp]
#pragma unroll
        for (int t = 0; t < 4; ++t) {
            const int s = rr + 32 * t;
            if (s < 121) {
                const int mi = s / 11;
                const int m2 = s - mi * 11;
                const int m1 = mi + cbase - m2;
                const bool ok = ((unsigned)m1 < n1u);
                const int m1c = ok ? m1 : 0;
                const float cgv = ok ? cgs[mi * 121 + m1c * 11 + m2] : 0.f;
                const ull  xv  = x1c64[par * 88 + m1c * 8 + bp];
                As[s * 8 + bp] = ok ? mul2(pack2(cgv), xv) : 0ull;
            }
        }
        __syncthreads();
        // ---- phase 2: build-GEMM: cat[d][mi][bp] = sum_m2 A[mi][m2]*x2[d][m2] ----
        {
            ull bacc[3][MS];
#pragma unroll
            for (int j = 0; j < 3; ++j)
#pragma unroll
                for (int mj = 0; mj < MS; ++mj) bacc[j][mj] = 0ull;
#pragma unroll
            for (int m2 = 0; m2 < 11; ++m2) {
                ull a[MS];
#pragma unroll
                for (int mj = 0; mj < MS; ++mj) {
                    const int mi = ms2 + 4 * mj;
                    if (mi < N) a[mj] = As[(mi * 11 + m2) * 8 + bp];
                }
#pragma unroll
                for (int j = 0; j < 3; ++j) {
                    const ull xv = x2s64[(dg * 3 + j) * 88 + m2 * 8 + bp];
#pragma unroll
                    for (int mj = 0; mj < MS; ++mj) {
                        const int mi = ms2 + 4 * mj;
                        if (mi < N) bacc[j][mj] = fma2(a[mj], xv, bacc[j][mj]);
                    }
                }
            }
#pragma unroll
            for (int j = 0; j < 3; ++j)
#pragma unroll
                for (int mj = 0; mj < MS; ++mj) {
                    const int mi = ms2 + 4 * mj;
                    if (mi < N) cats64[((dg * 3 + j) * N + mi) * 8 + bp] = bacc[j][mj];
                }
        }
        __syncthreads();
        // ---- phase 3: stage next x1 column + main GEMM ----
        if (cc + 1 < NCHUNK && tid < 16 * n1) {
            const int m1i = tid >> 4;
            const int b   = tid & 15;
            x1col[(par ^ 1) * 176 + m1i * 16 + b] =
                Xa[(b0 + b) * x1stride + (cc + 1) * n1 + m1i];
        }
#pragma unroll 4
        for (int k = 0; k < 24; ++k) {
            const float4 w = *reinterpret_cast<const float4*>(&Ws[k * 36 + hg * 4]);
            const ull w2[4] = { pack2(w.x), pack2(w.y), pack2(w.z), pack2(w.w) };
            const ull* __restrict__ cp = cats64 + k * (8 * N) + bp;
#pragma unroll
            for (int mj = 0; mj < MS; ++mj) {
                const int mi = ms + 4 * mj;
                if (mi < N) {                      // warp-uniform
                    const ull cv = cp[mi * 8];
                    acc[0][mj] = fma2(w2[0], cv, acc[0][mj]);
                    acc[1][mj] = fma2(w2[1], cv, acc[1][mj]);
                    acc[2][mj] = fma2(w2[2], cv, acc[2][mj]);
                    acc[3][mj] = fma2(w2[3], cv, acc[3][mj]);
                }
            }
        }
        __syncthreads();
    }

    // --- writeback: batches b0+2bp, b0+2bp+1 ---
    float* op = out + ((b0 + bp * 2) * 32 + hg * 4) * 36 + moff;
#pragma unroll
    for (int j = 0; j < 4; ++j) {
#pragma unroll
        for (int mj = 0; mj < MS; ++mj) {
            const int mi = ms + 4 * mj;
            if (mi < N) {
                float lo, hi;
                unpack2(acc[j][mj], lo, hi);
                atomicAdd(op + j * 36 + mi, lo);
                atomicAdd(op + 32 * 36 + j * 36 + mi, hi);
            }
        }
    }
}

__global__ void __launch_bounds__(BLK, 4) cg_main(
    const float* __restrict__ X0, const float* __restrict__ X1, const float* __restrict__ X2,
    const float* __restrict__ X3, const float* __restrict__ X4, const float* __restrict__ X5,
    const float* __restrict__ W0, const float* __restrict__ W1, const float* __restrict__ W2,
    const float* __restrict__ W3, const float* __restrict__ W4, const float* __restrict__ W5,
    const float* __restrict__ cg, float* __restrict__ out)
{
    extern __shared__ float sm[];
    float* x2s   = sm;
    float* cgs   = sm + 4224;
    float* Ws    = sm + 5556;
    float* x1col = sm + 6420;
    ull*   As    = (ull*)(sm + 6772);
    ull*   cats  = (ull*)(sm + 8708);

    const int item = blockIdx.x >> 4;          // 0..110 (l, pair)
    const int b0   = (blockIdx.x & 15) << 4;   // batch tile start

    // decode work item: l ordered 5,4,3,2,1,0 (big work first)
    int l = 0, l1 = 0, l2 = 0, pidx = 0;
    {
        int cur = 0;
        bool done = false;
        for (int oi = 0; oi < 6 && !done; ++oi) {
            int L = 5 - oi;
            int pi = 0;
            for (int a = 0; a <= 5 && !done; ++a) {
                for (int b2 = 0; b2 <= 5; ++b2) {
                    int dd = a - b2; if (dd < 0) dd = -dd;
                    if (dd <= L && L <= a + b2) {
                        if (cur == item) { l = L; l1 = a; l2 = b2; pidx = pi; done = true; break; }
                        ++cur; ++pi;
                    }
                }
            }
        }
    }

    const int n1 = 2 * l1 + 1, n2 = 2 * l2 + 1, n = 2 * l + 1;
    int KIN, moff;
    switch (l) {
        case 0: KIN = 3456;  moff = 0;  break;
        case 1: KIN = 8640;  moff = 1;  break;
        case 2: KIN = 12096; moff = 4;  break;
        case 3: KIN = 13824; moff = 9;  break;
        case 4: KIN = 13824; moff = 16; break;
        default: KIN = 12096; moff = 25; break;
    }
    const float* Xa = pick6(X0, X1, X2, X3, X4, X5, l1);
    const float* Xb = pick6(X0, X1, X2, X3, X4, X5, l2);
    const float* Wl = pick6(W0, W1, W2, W3, W4, W5, l);
    const int koff = pidx * 576;
    const int tid = threadIdx.x;

    // zero-init x2s and x1col (m2 loop reads full 0..10 range; avoid stale NaN bits)
    for (int i = tid; i < 4224; i += BLK) x2s[i] = 0.f;
    for (int i = tid; i < 352; i += BLK) x1col[i] = 0.f;
    __syncthreads();

    // load x2 tile: global (b,d,m2) -> smem [d][m2][b16]
    for (int i = tid; i < 16 * 24 * n2; i += BLK) {
        int b = i / (24 * n2);
        int r = i - b * 24 * n2;
        int d = r / n2;
        int m2 = r - d * n2;
        x2s[(d * 11 + m2) * 16 + b] = Xb[(b0 + b) * 24 * n2 + r];
    }
    // cg slab for (l1,l2,l): contiguous n*121 floats (zero-padded by construction)
    const float* cgp = cg + ((l1 * 6 + l2) * 6 + l) * 1331;
    for (int i = tid; i < n * 121; i += BLK) cgs[i] = cgp[i];
    // stage x1 column for cc=0 into buffer 0
    if (tid < 16 * n1) {
        const int m1i = tid >> 4;
        const int b   = tid & 15;
        x1col[m1i * 16 + b] = Xa[(b0 + b) * (24 * n1) + m1i];
    }
    __syncthreads();

    const int cbase = l1 + l2 - l;
    switch (l) {
        case 0: run_pair<1>(Xa, x2s, cgs, Ws, x1col, As, cats, Wl, KIN, koff, n1, cbase, out, b0, moff); break;
        case 1: run_pair<3>(Xa, x2s, cgs, Ws, x1col, As, cats, Wl, KIN, koff, n1, cbase, out, b0, moff); break;
        case 2: run_pair<5>(Xa, x2s, cgs, Ws, x1col, As, cats, Wl, KIN, koff, n1, cbase, out, b0, moff); break;
        case 3: run_pair<7>(Xa, x2s, cgs, Ws, x1col, As, cats, Wl, KIN, koff, n1, cbase, out, b0, moff); break;
        case 4: run_pair<9>(Xa, x2s, cgs, Ws, x1col, As, cats, Wl, KIN, koff, n1, cbase, out, b0, moff); break;
        default: run_pair<11>(Xa, x2s, cgs, Ws, x1col, As, cats, Wl, KIN, koff, n1, cbase, out, b0, moff); break;
    }
}

__global__ void zero_out_kernel(float* __restrict__ o, int nTot) {
    int i = blockIdx.x * 256 + threadIdx.x;
    if (i < nTot) o[i] = 0.f;
}

extern "C" void kernel_launch(void* const* d_in, const int* in_sizes, int n_in,
                              void* d_out, int out_size)
{
    const float* X[6];
    const float* W[6];
    for (int i = 0; i < 6; ++i) X[i] = (const float*)d_in[i];
    for (int i = 0; i < 6; ++i) W[i] = (const float*)d_in[6 + i];
    const float* cg = (const float*)d_in[12];
    float* out = (float*)d_out;

    const int nTot = 256 * 32 * 36;  // 294912
    zero_out_kernel<<<(nTot + 255) / 256, 256>>>(out, nTot);

    cudaFuncSetAttribute(cg_main, cudaFuncAttributeMaxDynamicSharedMemorySize, SMEM_BYTES);
    cg_main<<<111 * 16, BLK, SMEM_BYTES>>>(
        X[0], X[1], X[2], X[3], X[4], X[5],
        W[0], W[1], W[2], W[3], W[4], W[5],
        cg, out);
}

// round 10
// speedup vs baseline: 1.0611x; 1.0007x over previous
#include <cuda_runtime.h>

#define BLK 256
#define NCHUNK 24

// SMEM layout (floats):
//  x2s   : [24][11][16]      @ 0     (4224)  zero-init
//  cgs   : [11][11][11]      @ 4224  (1332, padded)
//  Ws    : [24 d][36 h-pad]  @ 5556  (864)
//  x1col : [2][11][16]       @ 6420  (352)   double-buffered, zero-init
//  As    : ull[121][8]       @ 6772  (1936)  A[mi][m2] = cg*x1
//  cats  : ull[24][N][8]     @ 8708  (4224 max @ N=11)
#define SMEM_FLOATS 12932
#define SMEM_BYTES (SMEM_FLOATS * 4)

typedef unsigned long long ull;

__device__ __forceinline__ ull pack2(float v) {
    ull r; asm("mov.b64 %0, {%1, %1};" : "=l"(r) : "f"(v)); return r;
}
__device__ __forceinline__ ull mul2(ull a, ull b) {
    ull r; asm("mul.rn.f32x2 %0, %1, %2;" : "=l"(r) : "l"(a), "l"(b)); return r;
}
__device__ __forceinline__ ull fma2(ull a, ull b, ull c) {
    ull r; asm("fma.rn.f32x2 %0, %1, %2, %3;" : "=l"(r) : "l"(a), "l"(b), "l"(c)); return r;
}
__device__ __forceinline__ void unpack2(ull v, float& lo, float& hi) {
    asm("mov.b64 {%0, %1}, %2;" : "=f"(lo), "=f"(hi) : "l"(v));
}

__device__ __forceinline__ const float* pick6(
    const float* a0, const float* a1, const float* a2,
    const float* a3, const float* a4, const float* a5, int l) {
    switch (l) {
        case 0: return a0; case 1: return a1; case 2: return a2;
        case 3: return a3; case 4: return a4; default: return a5;
    }
}

template <int N>
__device__ __forceinline__ void run_pair(
    const float* __restrict__ Xa,        // global x_{l1} (column staging)
    const float* __restrict__ x2s,
    const float* __restrict__ cgs,
    float* __restrict__ Ws,
    float* __restrict__ x1col,
    ull* __restrict__ As,
    ull* __restrict__ cats64,
    const float* __restrict__ Wl, int KIN, int koff,
    int n1, int n2, int cbase,
    float* __restrict__ out, int b0, int moff)
{
    const int tid = threadIdx.x;
    const int bp = tid & 7;          // batch pair 0..7 (f32x2)
    const int hg = (tid >> 3) & 7;   // h quad: h = hg*4 + j
    const int ms = tid >> 6;         // m slice 0..3 (GEMM): mi = ms + 4*mj
    const int rr = tid >> 3;         // 0..31 cursor
    const int dg  = rr >> 2;         // 0..7: d group (3 d each) for build-GEMM
    const int ms2 = rr & 3;          // 0..3: mi slice for build-GEMM

    constexpr int MS = (N + 3) / 4;
    ull acc[4][MS];
#pragma unroll
    for (int j = 0; j < 4; ++j)
#pragma unroll
        for (int mj = 0; mj < MS; ++mj) acc[j][mj] = 0ull;

    const ull* __restrict__ x2s64 = (const ull*)x2s;
    const ull* __restrict__ x1c64 = (const ull*)x1col;
    const unsigned n1u = (unsigned)n1;
    const int x1stride = 24 * n1;

#pragma unroll 1
    for (int cc = 0; cc < NCHUNK; ++cc) {
        const int par = cc & 1;
        // ---- phase 1: W chunk load + A build (only m2 < n2 slots are read) ----
#pragma unroll
        for (int i = tid; i < 768; i += BLK) {
            const int h = i / 24;
            const int d = i - h * 24;
            Ws[d * 36 + h] = Wl[h * KIN + koff + cc * 24 + d];
        }
        // A[mi][m2][bp] = cg[mi, m1=mi+cb-m2, m2] * x1[cc][m1][bp]
#pragma unroll
        for (int t = 0; t < 4; ++t) {
            const int s = rr + 32 * t;
            if (s < 121) {
                const int mi = s / 11;
                const int m2 = s - mi * 11;
                if (m2 < n2) {                    // slots m2>=n2 never read
                    const int m1 = mi + cbase - m2;
                    const bool ok = ((unsigned)m1 < n1u);
                    const int m1c = ok ? m1 : 0;
                    const float cgv = ok ? cgs[mi * 121 + m1c * 11 + m2] : 0.f;
                    const ull  xv  = x1c64[par * 88 + m1c * 8 + bp];
                    As[s * 8 + bp] = ok ? mul2(pack2(cgv), xv) : 0ull;
                }
            }
        }
        __syncthreads();
        // ---- phase 2: build-GEMM: cat[d][mi][bp] = sum_{m2<n2} A[mi][m2]*x2[d][m2] ----
        {
            ull bacc[3][MS];
#pragma unroll
            for (int j = 0; j < 3; ++j)
#pragma unroll
                for (int mj = 0; mj < MS; ++mj) bacc[j][mj] = 0ull;
#pragma unroll
            for (int m2 = 0; m2 < 11; ++m2) {
                if (m2 >= n2) break;              // CTA-uniform early exit
                ull a[MS];
#pragma unroll
                for (int mj = 0; mj < MS; ++mj) {
                    const int mi = ms2 + 4 * mj;
                    if (mi < N) a[mj] = As[(mi * 11 + m2) * 8 + bp];
                }
#pragma unroll
                for (int j = 0; j < 3; ++j) {
                    const ull xv = x2s64[(dg * 3 + j) * 88 + m2 * 8 + bp];
#pragma unroll
                    for (int mj = 0; mj < MS; ++mj) {
                        const int mi = ms2 + 4 * mj;
                        if (mi < N) bacc[j][mj] = fma2(a[mj], xv, bacc[j][mj]);
                    }
                }
            }
#pragma unroll
            for (int j = 0; j < 3; ++j)
#pragma unroll
                for (int mj = 0; mj < MS; ++mj) {
                    const int mi = ms2 + 4 * mj;
                    if (mi < N) cats64[((dg * 3 + j) * N + mi) * 8 + bp] = bacc[j][mj];
                }
        }
        __syncthreads();
        // ---- phase 3: stage next x1 column + main GEMM ----
        if (cc + 1 < NCHUNK && tid < 16 * n1) {
            const int m1i = tid >> 4;
            const int b   = tid & 15;
            x1col[(par ^ 1) * 176 + m1i * 16 + b] =
                Xa[(b0 + b) * x1stride + (cc + 1) * n1 + m1i];
        }
#pragma unroll 4
        for (int k = 0; k < 24; ++k) {
            const float4 w = *reinterpret_cast<const float4*>(&Ws[k * 36 + hg * 4]);
            const ull w2[4] = { pack2(w.x), pack2(w.y), pack2(w.z), pack2(w.w) };
            const ull* __restrict__ cp = cats64 + k * (8 * N) + bp;
#pragma unroll
            for (int mj = 0; mj < MS; ++mj) {
                const int mi = ms + 4 * mj;
                if (mi < N) {                      // warp-uniform
                    const ull cv = cp[mi * 8];
                    acc[0][mj] = fma2(w2[0], cv, acc[0][mj]);
                    acc[1][mj] = fma2(w2[1], cv, acc[1][mj]);
                    acc[2][mj] = fma2(w2[2], cv, acc[2][mj]);
                    acc[3][mj] = fma2(w2[3], cv, acc[3][mj]);
                }
            }
        }
        __syncthreads();
    }

    // --- writeback: batches b0+2bp, b0+2bp+1 ---
    float* op = out + ((b0 + bp * 2) * 32 + hg * 4) * 36 + moff;
#pragma unroll
    for (int j = 0; j < 4; ++j) {
#pragma unroll
        for (int mj = 0; mj < MS; ++mj) {
            const int mi = ms + 4 * mj;
            if (mi < N) {
                float lo, hi;
                unpack2(acc[j][mj], lo, hi);
                atomicAdd(op + j * 36 + mi, lo);
                atomicAdd(op + 32 * 36 + j * 36 + mi, hi);
            }
        }
    }
}

__global__ void __launch_bounds__(BLK, 4) cg_main(
    const float* __restrict__ X0, const float* __restrict__ X1, const float* __restrict__ X2,
    const float* __restrict__ X3, const float* __restrict__ X4, const float* __restrict__ X5,
    const float* __restrict__ W0, const float* __restrict__ W1, const float* __restrict__ W2,
    const float* __restrict__ W3, const float* __restrict__ W4, const float* __restrict__ W5,
    const float* __restrict__ cg, float* __restrict__ out)
{
    extern __shared__ float sm[];
    float* x2s   = sm;
    float* cgs   = sm + 4224;
    float* Ws    = sm + 5556;
    float* x1col = sm + 6420;
    ull*   As    = (ull*)(sm + 6772);
    ull*   cats  = (ull*)(sm + 8708);

    const int item = blockIdx.x >> 4;          // 0..110 (l, pair)
    const int b0   = (blockIdx.x & 15) << 4;   // batch tile start

    // decode work item: l ordered 5,4,3,2,1,0 (big work first)
    int l = 0, l1 = 0, l2 = 0, pidx = 0;
    {
        int cur = 0;
        bool done = false;
        for (int oi = 0; oi < 6 && !done; ++oi) {
            int L = 5 - oi;
            int pi = 0;
            for (int a = 0; a <= 5 && !done; ++a) {
                for (int b2 = 0; b2 <= 5; ++b2) {
                    int dd = a - b2; if (dd < 0) dd = -dd;
                    if (dd <= L && L <= a + b2) {
                        if (cur == item) { l = L; l1 = a; l2 = b2; pidx = pi; done = true; break; }
                        ++cur; ++pi;
                    }
                }
            }
        }
    }

    const int n1 = 2 * l1 + 1, n2 = 2 * l2 + 1, n = 2 * l + 1;
    int KIN, moff;
    switch (l) {
        case 0: KIN = 3456;  moff = 0;  break;
        case 1: KIN = 8640;  moff = 1;  break;
        case 2: KIN = 12096; moff = 4;  break;
        case 3: KIN = 13824; moff = 9;  break;
        case 4: KIN = 13824; moff = 16; break;
        default: KIN = 12096; moff = 25; break;
    }
    const float* Xa = pick6(X0, X1, X2, X3, X4, X5, l1);
    const float* Xb = pick6(X0, X1, X2, X3, X4, X5, l2);
    const float* Wl = pick6(W0, W1, W2, W3, W4, W5, l);
    const int koff = pidx * 576;
    const int tid = threadIdx.x;

    // zero-init x2s and x1col (defensive; phase loops now bounded by n2/n1)
    for (int i = tid; i < 4224; i += BLK) x2s[i] = 0.f;
    for (int i = tid; i < 352; i += BLK) x1col[i] = 0.f;
    __syncthreads();

    // load x2 tile: global (b,d,m2) -> smem [d][m2][b16]
    for (int i = tid; i < 16 * 24 * n2; i += BLK) {
        int b = i / (24 * n2);
        int r = i - b * 24 * n2;
        int d = r / n2;
        int m2 = r - d * n2;
        x2s[(d * 11 + m2) * 16 + b] = Xb[(b0 + b) * 24 * n2 + r];
    }
    // cg slab for (l1,l2,l): contiguous n*121 floats (zero-padded by construction)
    const float* cgp = cg + ((l1 * 6 + l2) * 6 + l) * 1331;
    for (int i = tid; i < n * 121; i += BLK) cgs[i] = cgp[i];
    // stage x1 column for cc=0 into buffer 0
    if (tid < 16 * n1) {
        const int m1i = tid >> 4;
        const int b   = tid & 15;
        x1col[m1i * 16 + b] = Xa[(b0 + b) * (24 * n1) + m1i];
    }
    __syncthreads();

    const int cbase = l1 + l2 - l;
    switch (l) {
        case 0: run_pair<1>(Xa, x2s, cgs, Ws, x1col, As, cats, Wl, KIN, koff, n1, n2, cbase, out, b0, moff); break;
        case 1: run_pair<3>(Xa, x2s, cgs, Ws, x1col, As, cats, Wl, KIN, koff, n1, n2, cbase, out, b0, moff); break;
        case 2: run_pair<5>(Xa, x2s, cgs, Ws, x1col, As, cats, Wl, KIN, koff, n1, n2, cbase, out, b0, moff); break;
        case 3: run_pair<7>(Xa, x2s, cgs, Ws, x1col, As, cats, Wl, KIN, koff, n1, n2, cbase, out, b0, moff); break;
        case 4: run_pair<9>(Xa, x2s, cgs, Ws, x1col, As, cats, Wl, KIN, koff, n1, n2, cbase, out, b0, moff); break;
        default: run_pair<11>(Xa, x2s, cgs, Ws, x1col, As, cats, Wl, KIN, koff, n1, n2, cbase, out, b0, moff); break;
    }
}

__global__ void zero_out_kernel(float* __restrict__ o, int nTot) {
    int i = blockIdx.x * 256 + threadIdx.x;
    if (i < nTot) o[i] = 0.f;
}

extern "C" void kernel_launch(void* const* d_in, const int* in_sizes, int n_in,
                              void* d_out, int out_size)
{
    const float* X[6];
    const float* W[6];
    for (int i = 0; i < 6; ++i) X[i] = (const float*)d_in[i];
    for (int i = 0; i < 6; ++i) W[i] = (const float*)d_in[6 + i];
    const float* cg = (const float*)d_in[12];
    float* out = (float*)d_out;

    const int nTot = 256 * 32 * 36;  // 294912
    zero_out_kernel<<<(nTot + 255) / 256, 256>>>(out, nTot);

    cudaFuncSetAttribute(cg_main, cudaFuncAttributeMaxDynamicSharedMemorySize, SMEM_BYTES);
    cg_main<<<111 * 16, BLK, SMEM_BYTES>>>(
        X[0], X[1], X[2], X[3], X[4], X[5],
        W[0], W[1], W[2], W[3], W[4], W[5],
        cg, out);
}

// round 12
// speedup vs baseline: 1.7019x; 1.6040x over previous
#include <cuda_runtime.h>

#define BLK 256
#define NCHUNK 24

// byte offsets in dynamic smem
#define SCAT 0        // cat tf32: [24 k][184 bm-pad] u32 = 17664 B
#define SW   17664    // W tf32:   [32 h][28 k-pad]  u32 = 3584 B
#define SX2  21248    // x2s: [24][11][16] f32 = 16896 B
#define SCG  38144    // cgs: 1332 f32 = 5328 B
#define SX1  43472    // x1col: [2][11][16] f32 = 1408 B
#define SAS  44880    // As: ull[121][8] = 7744 B
#define SMEM_BYTES 52624

typedef unsigned long long ull;
typedef unsigned int u32;

__device__ __forceinline__ ull pack2(float v) {
    ull r; asm("mov.b64 %0, {%1, %1};" : "=l"(r) : "f"(v)); return r;
}
__device__ __forceinline__ ull mul2(ull a, ull b) {
    ull r; asm("mul.rn.f32x2 %0, %1, %2;" : "=l"(r) : "l"(a), "l"(b)); return r;
}
__device__ __forceinline__ ull fma2(ull a, ull b, ull c) {
    ull r; asm("fma.rn.f32x2 %0, %1, %2, %3;" : "=l"(r) : "l"(a), "l"(b), "l"(c)); return r;
}
__device__ __forceinline__ void unpack2(ull v, float& lo, float& hi) {
    asm("mov.b64 {%0, %1}, %2;" : "=f"(lo), "=f"(hi) : "l"(v));
}
__device__ __forceinline__ u32 tf32c(float f) {
    u32 r; asm("cvt.rna.tf32.f32 %0, %1;" : "=r"(r) : "f"(f)); return r;
}
__device__ __forceinline__ ull packu(u32 lo, u32 hi) {
    ull r; asm("mov.b64 %0, {%1, %2};" : "=l"(r) : "r"(lo), "r"(hi)); return r;
}

#define MMA_TF32(d, a, bb0, bb1) \
    asm volatile("mma.sync.aligned.m16n8k8.row.col.f32.tf32.tf32.f32 " \
        "{%0,%1,%2,%3}, {%4,%5,%6,%7}, {%8,%9}, {%0,%1,%2,%3};" \
        : "+f"((d)[0]), "+f"((d)[1]), "+f"((d)[2]), "+f"((d)[3]) \
        : "r"((a)[0]), "r"((a)[1]), "r"((a)[2]), "r"((a)[3]), "r"(bb0), "r"(bb1))

__device__ __forceinline__ const float* pick6(
    const float* a0, const float* a1, const float* a2,
    const float* a3, const float* a4, const float* a5, int l) {
    switch (l) {
        case 0: return a0; case 1: return a1; case 2: return a2;
        case 3: return a3; case 4: return a4; default: return a5;
    }
}

template <int N>
__device__ __forceinline__ void run_pair(
    const float* __restrict__ Xa, char* smem,
    const float* __restrict__ Wl, int KIN, int koff,
    int n1, int n2, int cbase,
    float* __restrict__ out, int b0, int moff)
{
    constexpr int NT = 2 * N;        // number of n8 tiles over bm = 16*N
    constexpr int MS = (N + 3) / 4;
    const int tid  = threadIdx.x;
    const int lane = tid & 31;
    const int w    = tid >> 5;       // warp 0..7 (= dg in cat build)
    const int bp   = tid & 7;        // batch pair lane (f32x2)
    const int rr   = tid >> 3;
    const int ms2  = rr & 3;         // mi slice in cat build
    const int mt     = w & 1;        // m16 tile over h (0..1)
    const int ntbase = w >> 1;       // n-tile base (stride 4)

    u32*  __restrict__ catT = (u32*)(smem + SCAT);
    u32*  __restrict__ WsU  = (u32*)(smem + SW);
    const ull* __restrict__ x2s64 = (const ull*)(smem + SX2);
    const ull* __restrict__ x1c64 = (const ull*)(smem + SX1);
    const float* __restrict__ cgs = (const float*)(smem + SCG);
    float* __restrict__ x1col = (float*)(smem + SX1);
    ull* __restrict__ As = (ull*)(smem + SAS);
    const unsigned n1u = (unsigned)n1;
    const int x1stride = 24 * n1;

    float acc[6][4];
#pragma unroll
    for (int j = 0; j < 6; ++j)
#pragma unroll
        for (int r = 0; r < 4; ++r) acc[j][r] = 0.f;

#pragma unroll 1
    for (int cc = 0; cc < NCHUNK; ++cc) {
        const int par = cc & 1;
        // ---- phase 1: W -> tf32 [h][28], A-factor build, x1 staging ----
#pragma unroll
        for (int t = 0; t < 2; ++t) {
            const int i = tid + 256 * t;
            if (i < 384) {                       // 32 h x 12 float2
                const int h  = i / 12;
                const int kp = i - h * 12;
                const float2 wv = *reinterpret_cast<const float2*>(
                    Wl + h * KIN + koff + cc * 24 + kp * 2);
                WsU[h * 28 + kp * 2]     = tf32c(wv.x);
                WsU[h * 28 + kp * 2 + 1] = tf32c(wv.y);
            }
        }
        // A[mi][m2][bp] = cg[mi, m1=mi+cb-m2, m2] * x1[cc][m1][bp]  (f32x2)
#pragma unroll
        for (int t = 0; t < 4; ++t) {
            const int s = rr + 32 * t;
            if (s < 121) {
                const int mi = s / 11;
                const int m2 = s - mi * 11;
                if (m2 < n2) {
                    const int m1 = mi + cbase - m2;
                    const bool ok = ((unsigned)m1 < n1u);
                    const int m1c = ok ? m1 : 0;
                    const float cgv = ok ? cgs[mi * 121 + m1c * 11 + m2] : 0.f;
                    const ull  xv  = x1c64[par * 88 + m1c * 8 + bp];
                    As[s * 8 + bp] = ok ? mul2(pack2(cgv), xv) : 0ull;
                }
            }
        }
        if (cc + 1 < NCHUNK && tid < 16 * n1) {
            const int m1i = tid >> 4;
            const int b   = tid & 15;
            x1col[(par ^ 1) * 176 + m1i * 16 + b] =
                Xa[(b0 + b) * x1stride + (cc + 1) * n1 + m1i];
        }
        __syncthreads();
        // ---- phase 2: cat build (R10 math) -> tf32 [k][bm], k=w*3+j ----
        {
            ull bacc[3][MS];
#pragma unroll
            for (int j = 0; j < 3; ++j)
#pragma unroll
                for (int mj = 0; mj < MS; ++mj) bacc[j][mj] = 0ull;
#pragma unroll
            for (int m2 = 0; m2 < 11; ++m2) {
                if (m2 >= n2) break;              // CTA-uniform
                ull a[MS];
#pragma unroll
                for (int mj = 0; mj < MS; ++mj) {
                    const int mi = ms2 + 4 * mj;
                    if (mi < N) a[mj] = As[(mi * 11 + m2) * 8 + bp];
                }
#pragma unroll
                for (int j = 0; j < 3; ++j) {
                    const ull xv = x2s64[(w * 3 + j) * 88 + m2 * 8 + bp];
#pragma unroll
                    for (int mj = 0; mj < MS; ++mj) {
                        const int mi = ms2 + 4 * mj;
                        if (mi < N) bacc[j][mj] = fma2(a[mj], xv, bacc[j][mj]);
                    }
                }
            }
#pragma unroll
            for (int j = 0; j < 3; ++j) {
                const int k = w * 3 + j;
#pragma unroll
                for (int mj = 0; mj < MS; ++mj) {
                    const int mi = ms2 + 4 * mj;
                    if (mi < N) {
                        float lo, hi;
                        unpack2(bacc[j][mj], lo, hi);
                        // bm = mi*16 + 2bp(+1); STS.64 of two tf32
                        *reinterpret_cast<ull*>(catT + k * 184 + mi * 16 + 2 * bp) =
                            packu(tf32c(lo), tf32c(hi));
                    }
                }
            }
        }
        __syncthreads();
        // ---- phase 3: tf32 MMA GEMM: D[h][bm] += W[h][k] * cat[k][bm] ----
#pragma unroll
        for (int ks = 0; ks < 3; ++ks) {
            u32 a[4];
            {
                const int row = mt * 16 + (lane >> 2);
                const int col = ks * 8 + (lane & 3);
                a[0] = WsU[row * 28 + col];
                a[1] = WsU[(row + 8) * 28 + col];
                a[2] = WsU[row * 28 + col + 4];
                a[3] = WsU[(row + 8) * 28 + col + 4];
            }
            const int kr = ks * 8 + (lane & 3);
#pragma unroll
            for (int j = 0; j < 6; ++j) {
                const int nt = ntbase + 4 * j;
                if (nt < NT) {                    // warp-uniform
                    const int cb = nt * 8 + (lane >> 2);
                    const u32 b0v = catT[kr * 184 + cb];
                    const u32 b1v = catT[(kr + 4) * 184 + cb];
                    MMA_TF32(acc[j], a, b0v, b1v);
                }
            }
        }
        __syncthreads();
    }

    // ---- epilogue: fragments -> atomicAdd ----
#pragma unroll
    for (int j = 0; j < 6; ++j) {
        const int nt = ntbase + 4 * j;
        if (nt < NT) {
            const int hrow = mt * 16 + (lane >> 2);
            const int cb   = nt * 8 + 2 * (lane & 3);
#pragma unroll
            for (int r = 0; r < 4; ++r) {
                const int h  = hrow + ((r >> 1) << 3);
                const int bm = cb + (r & 1);
                const int b  = bm & 15;
                const int mi = bm >> 4;
                atomicAdd(out + (u32)(b0 + b) * 1152 + h * 36 + moff + mi, acc[j][r]);
            }
        }
    }
}

__global__ void __launch_bounds__(BLK, 4) cg_main(
    const float* __restrict__ X0, const float* __restrict__ X1, const float* __restrict__ X2,
    const float* __restrict__ X3, const float* __restrict__ X4, const float* __restrict__ X5,
    const float* __restrict__ W0, const float* __restrict__ W1, const float* __restrict__ W2,
    const float* __restrict__ W3, const float* __restrict__ W4, const float* __restrict__ W5,
    const float* __restrict__ cg, float* __restrict__ out)
{
    extern __shared__ char smem[];

    const int item = blockIdx.x >> 4;
    const int b0   = (blockIdx.x & 15) << 4;
    const int tid  = threadIdx.x;

    // decode work item: l ordered 5,4,3,2,1,0
    int l = 0, l1 = 0, l2 = 0, pidx = 0;
    {
        int cur = 0;
        bool done = false;
        for (int oi = 0; oi < 6 && !done; ++oi) {
            int L = 5 - oi;
            int pi = 0;
            for (int a = 0; a <= 5 && !done; ++a) {
                for (int b2 = 0; b2 <= 5; ++b2) {
                    int dd = a - b2; if (dd < 0) dd = -dd;
                    if (dd <= L && L <= a + b2) {
                        if (cur == item) { l = L; l1 = a; l2 = b2; pidx = pi; done = true; break; }
                        ++cur; ++pi;
                    }
                }
            }
        }
    }

    const int n1 = 2 * l1 + 1, n2 = 2 * l2 + 1, n = 2 * l + 1;
    int KIN, moff;
    switch (l) {
        case 0: KIN = 3456;  moff = 0;  break;
        case 1: KIN = 8640;  moff = 1;  break;
        case 2: KIN = 12096; moff = 4;  break;
        case 3: KIN = 13824; moff = 9;  break;
        case 4: KIN = 13824; moff = 16; break;
        default: KIN = 12096; moff = 25; break;
    }
    const float* Xa = pick6(X0, X1, X2, X3, X4, X5, l1);
    const float* Xb = pick6(X0, X1, X2, X3, X4, X5, l2);
    const float* Wl = pick6(W0, W1, W2, W3, W4, W5, l);
    const int koff = pidx * 576;

    // x2 tile: global (b,d,m2) -> smem [d][m2][b16]
    float* x2s = (float*)(smem + SX2);
    for (int i = tid; i < 16 * 24 * n2; i += BLK) {
        int b = i / (24 * n2);
        int r = i - b * 24 * n2;
        int d = r / n2;
        int m2 = r - d * n2;
        x2s[(d * 11 + m2) * 16 + b] = Xb[(b0 + b) * 24 * n2 + r];
    }
    // cg slab
    float* cgs = (float*)(smem + SCG);
    const float* cgp = cg + ((l1 * 6 + l2) * 6 + l) * 1331;
    for (int i = tid; i < n * 121; i += BLK) cgs[i] = cgp[i];
    // x1 column cc=0 into buffer 0
    float* x1col = (float*)(smem + SX1);
    if (tid < 16 * n1) {
        const int m1i = tid >> 4;
        const int b   = tid & 15;
        x1col[m1i * 16 + b] = Xa[(b0 + b) * (24 * n1) + m1i];
    }
    __syncthreads();

    const int cbase = l1 + l2 - l;
    switch (l) {
        case 0: run_pair<1>(Xa, smem, Wl, KIN, koff, n1, n2, cbase, out, b0, moff); break;
        case 1: run_pair<3>(Xa, smem, Wl, KIN, koff, n1, n2, cbase, out, b0, moff); break;
        case 2: run_pair<5>(Xa, smem, Wl, KIN, koff, n1, n2, cbase, out, b0, moff); break;
        case 3: run_pair<7>(Xa, smem, Wl, KIN, koff, n1, n2, cbase, out, b0, moff); break;
        case 4: run_pair<9>(Xa, smem, Wl, KIN, koff, n1, n2, cbase, out, b0, moff); break;
        default: run_pair<11>(Xa, smem, Wl, KIN, koff, n1, n2, cbase, out, b0, moff); break;
    }
}

__global__ void zero_out_kernel(float* __restrict__ o, int nTot) {
    int i = blockIdx.x * 256 + threadIdx.x;
    if (i < nTot) o[i] = 0.f;
}

extern "C" void kernel_launch(void* const* d_in, const int* in_sizes, int n_in,
                              void* d_out, int out_size)
{
    const float* X[6];
    const float* W[6];
    for (int i = 0; i < 6; ++i) X[i] = (const float*)d_in[i];
    for (int i = 0; i < 6; ++i) W[i] = (const float*)d_in[6 + i];
    const float* cg = (const float*)d_in[12];
    float* out = (float*)d_out;

    const int nTot = 256 * 32 * 36;  // 294912
    zero_out_kernel<<<(nTot + 255) / 256, 256>>>(out, nTot);

    cudaFuncSetAttribute(cg_main, cudaFuncAttributeMaxDynamicSharedMemorySize, SMEM_BYTES);
    cg_main<<<111 * 16, BLK, SMEM_BYTES>>>(
        X[0], X[1], X[2], X[3], X[4], X[5],
        W[0], W[1], W[2], W[3], W[4], W[5],
        cg, out);
}